// round 3
// baseline (speedup 1.0000x reference)
#include <cuda_runtime.h>
#include <cuda_bf16.h>
#include <stdint.h>

// Problem constants (fixed by setup_inputs)
#define NN     256
#define CC     3
#define TT     300
#define VV     25
#define MM     2
#define DD     256
#define KK     5
#define TOPK   64
#define NROWS  (NN*MM*TT)        // 153600
#define VMVM   (VV*MM)           // 50
#define SELSZ  (NN*CC*TOPK*VMVM) // 2457600
#define EPSF   1e-8f

// ---------------- scratch (device globals; no allocation allowed) ----------------
__device__ float g_sums[KK*DD];
__device__ float g_counts[KK];
__device__ float g_mean[KK*DD];
__device__ float g_inter[KK];
__device__ float g_Sb;
__device__ float g_Sw;
__device__ float g_VF[NN*TT];
__device__ int   g_idx[NN*TOPK];

// ---------------- kernel 0: zero accumulators ----------------
__global__ void k_zero() {
    int i = blockIdx.x * blockDim.x + threadIdx.x;
    if (i < KK*DD) g_sums[i] = 0.f;
    if (i < KK)    g_counts[i] = 0.f;
    if (i == 0)  { g_Sw = 0.f; }
    if (i < NN*TT) g_VF[i] = 0.f;
}

// ---------------- kernel 1: segment sums + counts ----------------
// thread d owns column d; labels uniform across the block -> predicated reg accumulators.
#define ROWS_PER_BLOCK 256
__global__ void k_segsum(const float* __restrict__ xT, const int* __restrict__ labels) {
    const int d = threadIdx.x;
    const int row0 = blockIdx.x * ROWS_PER_BLOCK;
    float acc[KK] = {0.f, 0.f, 0.f, 0.f, 0.f};
    float cnt[KK] = {0.f, 0.f, 0.f, 0.f, 0.f};
    #pragma unroll 4
    for (int i = 0; i < ROWS_PER_BLOCK; i++) {
        const int r = row0 + i;
        const int l = __ldg(&labels[r]);
        const float v = xT[(size_t)r * DD + d];
        #pragma unroll
        for (int k = 0; k < KK; k++) {
            if (l == k) acc[k] += v;
            if (d == 0 && l == k) cnt[k] += 1.f;
        }
    }
    #pragma unroll
    for (int k = 0; k < KK; k++)
        atomicAdd(&g_sums[k*DD + d], acc[k]);
    if (d == 0) {
        #pragma unroll
        for (int k = 0; k < KK; k++)
            atomicAdd(&g_counts[k], cnt[k]);
    }
}

// ---------------- kernel 2: class means, overall mean, inter, Sb (1 block) ----------------
__global__ void k_classstats() {
    const int d = threadIdx.x;             // 256 threads
    __shared__ float red[DD];
    float mean[KK];
    float tot = 0.f;
    #pragma unroll
    for (int k = 0; k < KK; k++) {
        float s = g_sums[k*DD + d];
        float c = g_counts[k];
        tot += s;
        mean[k] = s / fmaxf(c, 1.f);
        g_mean[k*DD + d] = mean[k];
    }
    const float om = tot / (float)NROWS;
    float interloc[KK];
    #pragma unroll
    for (int k = 0; k < KK; k++) {
        float df = mean[k] - om;
        red[d] = df * df;
        __syncthreads();
        for (int off = DD/2; off > 0; off >>= 1) {
            if (d < off) red[d] += red[d + off];
            __syncthreads();
        }
        interloc[k] = red[0];
        __syncthreads();
    }
    if (d == 0) {
        float sb = 0.f;
        #pragma unroll
        for (int k = 0; k < KK; k++) {
            g_inter[k] = interloc[k];
            sb += g_counts[k] * interloc[k];
        }
        g_Sb = sb;
    }
}

// ---------------- kernel 3: intra per row, Sw, frame scores into VF ----------------
// warp per row; 8 warps/block; each warp handles ROWS_PER_WARP rows.
#define ROWS_PER_WARP 16
__global__ void k_intra(const float* __restrict__ xT, const int* __restrict__ labels) {
    __shared__ float smean[KK*DD];
    __shared__ float sinter[KK];
    __shared__ float sSw[8];
    const int tid = threadIdx.x;
    for (int i = tid; i < KK*DD; i += blockDim.x) smean[i] = g_mean[i];
    if (tid < KK) sinter[tid] = g_inter[tid];
    __syncthreads();

    const int lane = tid & 31;
    const int wInB = tid >> 5;
    const int warp = blockIdx.x * 8 + wInB;
    float swAcc = 0.f;

    #pragma unroll 1
    for (int rr = 0; rr < ROWS_PER_WARP; rr++) {
        const int r = warp * ROWS_PER_WARP + rr;
        const int l = __ldg(&labels[r]);
        const float* xp = xT + (size_t)r * DD;
        float s = 0.f;
        #pragma unroll
        for (int j = 0; j < 8; j++) {
            const int c = lane + 32*j;
            const float df = xp[c] - smean[l*DD + c];
            s += df * df;
        }
        #pragma unroll
        for (int off = 16; off > 0; off >>= 1)
            s += __shfl_xor_sync(0xFFFFFFFFu, s, off);
        if (lane == 0) {
            swAcc += s;
            const float score = sinter[l] / (s + EPSF);
            const int n = r / (MM*TT);
            const int t = r % TT;
            atomicAdd(&g_VF[n*TT + t], score);   // sums over M; /M skipped (ranking-invariant)
        }
    }
    if (lane == 0) sSw[wInB] = swAcc;
    __syncthreads();
    if (tid == 0) {
        float b = 0.f;
        #pragma unroll
        for (int w = 0; w < 8; w++) b += sSw[w];
        atomicAdd(&g_Sw, b);
    }
}

// ---------------- kernel 4: loss ----------------
__global__ void k_loss(float* __restrict__ out_loss) {
    if (threadIdx.x == 0) out_loss[0] = g_Sw / (g_Sb + EPSF);
}

// ---------------- kernel 5: per-sample top-64 of 300, ascending indices ----------------
// Replicates jax.lax.top_k tie-break (smaller index wins on equal value), then sort asc.
__global__ void k_topk() {
    __shared__ float v[TT];
    __shared__ int   sel[TT];
    const int n = blockIdx.x;
    const int t = threadIdx.x;          // 320 threads
    if (t < TT) v[t] = g_VF[n*TT + t];
    __syncthreads();
    if (t < TT) {
        const float mv = v[t];
        int cnt = 0;
        #pragma unroll 4
        for (int u = 0; u < TT; u++) {
            const float vu = v[u];
            cnt += (vu > mv) || (vu == mv && u < t);
        }
        sel[t] = (cnt < TOPK) ? 1 : 0;
    }
    __syncthreads();
    if (t < TT && sel[t]) {
        int pos = 0;
        for (int u = 0; u < t; u++) pos += sel[u];
        g_idx[n*TOPK + pos] = t;
    }
}

// ---------------- kernel 6: gather selected frames ----------------
// out[n,c,j,v,m] = x[n,c,idx[n,j],v,m]; inner V*M=50 contiguous.
__global__ void k_gather(const float* __restrict__ x, float* __restrict__ out) {
    const int o = blockIdx.x * blockDim.x + threadIdx.x;
    if (o >= SELSZ) return;
    const int r     = o % VMVM;
    const int chunk = o / VMVM;          // (n*CC + c)*TOPK + j
    const int j  = chunk % TOPK;
    const int nc = chunk / TOPK;         // n*CC + c
    const int n  = nc / CC;
    const int tsel = g_idx[n*TOPK + j];
    out[o] = x[((size_t)nc * TT + tsel) * VMVM + r];
}

// ---------------- launch ----------------
extern "C" void kernel_launch(void* const* d_in, const int* in_sizes, int n_in,
                              void* d_out, int out_size) {
    // Match inputs by element count (robust to scalar args / ordering).
    const float* x  = nullptr;
    const float* xT = nullptr;
    const int* labels = nullptr;
    for (int i = 0; i < n_in; i++) {
        if (in_sizes[i] == NN*CC*TT*VV*MM) x = (const float*)d_in[i];
        else if (in_sizes[i] == NROWS*DD)  xT = (const float*)d_in[i];
        else if (in_sizes[i] == NROWS)     labels = (const int*)d_in[i];
    }
    float* out = (float*)d_out;
    // Flattened tuple (loss, x_select): loss scalar first, selection block at tail.
    int sel_off = out_size - SELSZ;
    if (sel_off < 0) sel_off = 0;
    float* out_loss = out;
    float* out_sel  = out + sel_off;

    k_zero<<<(NN*TT + 255)/256, 256>>>();
    k_segsum<<<NROWS/ROWS_PER_BLOCK, 256>>>(xT, labels);
    k_classstats<<<1, 256>>>();
    k_intra<<<NROWS/(8*ROWS_PER_WARP), 256>>>(xT, labels);
    k_loss<<<1, 32>>>(out_loss);
    k_topk<<<NN, 320>>>();
    k_gather<<<(SELSZ + 255)/256, 256>>>(x, out_sel);
}